// round 11
// baseline (speedup 1.0000x reference)
#include <cuda_runtime.h>
#include <cstdint>
#include <stdint.h>
#include <math.h>

// Problem constants
#define B_  4
#define T_  4096
#define C_  1024
#define H_  16
#define D_  64
#define CS_ 64
#define NC_ 64
#define M_  (B_ * T_)      // 16384
#define F_  (3 * C_)       // 3072

// Scratch: qkv [B,T,3C] = 192MB, y [B,T,C] = 64MB (device globals — no allocs)
__device__ float g_qkv[50331648];   // 4*4096*3072
__device__ float g_y[16777216];     // 4*4096*1024

__device__ __forceinline__ uint32_t f2tf32(float f) {
    uint32_t u;
    asm("cvt.rna.tf32.f32 %0, %1;" : "=r"(u) : "f"(f));
    return u;
}

#define MMA_TF32(d, a, b)                                                     \
    asm volatile(                                                             \
        "mma.sync.aligned.m16n8k8.row.col.f32.tf32.tf32.f32 "                 \
        "{%0,%1,%2,%3}, {%4,%5,%6,%7}, {%8,%9}, {%0,%1,%2,%3};"               \
        : "+f"(d[0]), "+f"(d[1]), "+f"(d[2]), "+f"(d[3])                      \
        : "r"(a[0]), "r"(a[1]), "r"(a[2]), "r"(a[3]), "r"(b[0]), "r"(b[1]))

// ---------------------------------------------------------------------------
// TN GEMM via tensor cores (3xTF32): A [M,K] rm, B [N,K] rm, C = A @ B^T.
// 128x128 block tile, BK=16, 256 threads (8 warps as 4m x 2n, warp 32x64).
// Smem k-major [16][136] (pad 136 -> conflict-free fragment reads).
// ---------------------------------------------------------------------------
__global__ void __launch_bounds__(256, 1) gemm_tn_tc(const float* __restrict__ A,
                                                     const float* __restrict__ B,
                                                     float* __restrict__ C,
                                                     int M, int N, int K)
{
    __shared__ float As_hi[16][136];
    __shared__ float As_lo[16][136];
    __shared__ float Bs_hi[16][136];
    __shared__ float Bs_lo[16][136];

    const int tid  = threadIdx.x;
    const int row0 = blockIdx.y * 128;
    const int col0 = blockIdx.x * 128;

    const int lane = tid & 31;
    const int warp = tid >> 5;
    const int gid  = lane >> 2;     // 0..7
    const int tig  = lane & 3;      // 0..3
    const int wm   = warp & 3;      // 0..3 -> m offset
    const int wn   = warp >> 2;     // 0..1 -> n offset
    const int mb   = wm * 32;
    const int nb   = wn * 64;

    // global-load mapping: thread handles one (row, 4k) quad, x2 passes
    const int lr  = tid >> 2;          // 0..63 (pass adds +64)
    const int lc4 = (tid & 3) << 2;    // 0,4,8,12

    float acc[2][8][4];
#pragma unroll
    for (int i = 0; i < 2; i++)
#pragma unroll
        for (int j = 0; j < 8; j++)
#pragma unroll
            for (int r = 0; r < 4; r++) acc[i][j][r] = 0.0f;

    for (int k0 = 0; k0 < K; k0 += 16) {
#pragma unroll
        for (int it = 0; it < 2; it++) {
            int r = lr + it * 64;
            float4 a = *(const float4*)(A + (size_t)(row0 + r) * K + k0 + lc4);
            float4 b = *(const float4*)(B + (size_t)(col0 + r) * K + k0 + lc4);
            float av[4] = {a.x, a.y, a.z, a.w};
            float bv[4] = {b.x, b.y, b.z, b.w};
#pragma unroll
            for (int q = 0; q < 4; q++) {
                float ah = __uint_as_float(f2tf32(av[q]));
                float bh = __uint_as_float(f2tf32(bv[q]));
                As_hi[lc4 + q][r] = ah;
                As_lo[lc4 + q][r] = __uint_as_float(f2tf32(av[q] - ah));
                Bs_hi[lc4 + q][r] = bh;
                Bs_lo[lc4 + q][r] = __uint_as_float(f2tf32(bv[q] - bh));
            }
        }
        __syncthreads();

#pragma unroll
        for (int kk = 0; kk < 16; kk += 8) {
            uint32_t ah[2][4], al[2][4], bh[8][2], bl[8][2];
#pragma unroll
            for (int i = 0; i < 2; i++) {
                int m0 = mb + i * 16 + gid;
                ah[i][0] = __float_as_uint(As_hi[kk + tig][m0]);
                ah[i][1] = __float_as_uint(As_hi[kk + tig][m0 + 8]);
                ah[i][2] = __float_as_uint(As_hi[kk + tig + 4][m0]);
                ah[i][3] = __float_as_uint(As_hi[kk + tig + 4][m0 + 8]);
                al[i][0] = __float_as_uint(As_lo[kk + tig][m0]);
                al[i][1] = __float_as_uint(As_lo[kk + tig][m0 + 8]);
                al[i][2] = __float_as_uint(As_lo[kk + tig + 4][m0]);
                al[i][3] = __float_as_uint(As_lo[kk + tig + 4][m0 + 8]);
            }
#pragma unroll
            for (int j = 0; j < 8; j++) {
                int n0 = nb + j * 8 + gid;
                bh[j][0] = __float_as_uint(Bs_hi[kk + tig][n0]);
                bh[j][1] = __float_as_uint(Bs_hi[kk + tig + 4][n0]);
                bl[j][0] = __float_as_uint(Bs_lo[kk + tig][n0]);
                bl[j][1] = __float_as_uint(Bs_lo[kk + tig + 4][n0]);
            }
#pragma unroll
            for (int i = 0; i < 2; i++)
#pragma unroll
                for (int j = 0; j < 8; j++) {
                    MMA_TF32(acc[i][j], ah[i], bh[j]);   // hi*hi
                    MMA_TF32(acc[i][j], ah[i], bl[j]);   // hi*lo
                    MMA_TF32(acc[i][j], al[i], bh[j]);   // lo*hi
                }
        }
        __syncthreads();
    }

    // epilogue: c0,c1 at (row, col..col+1); c2,c3 at (row+8, col..col+1)
#pragma unroll
    for (int i = 0; i < 2; i++) {
        int row = row0 + mb + i * 16 + gid;
#pragma unroll
        for (int j = 0; j < 8; j++) {
            int col = col0 + nb + j * 8 + tig * 2;
            *(float2*)(C + (size_t)row * N + col) =
                make_float2(acc[i][j][0], acc[i][j][1]);
            *(float2*)(C + (size_t)(row + 8) * N + col) =
                make_float2(acc[i][j][2], acc[i][j][3]);
        }
    }
}

// ---------------------------------------------------------------------------
// Fused chunked attention: one block per (b, chunk, head).
// ---------------------------------------------------------------------------
__global__ void __launch_bounds__(256) attn_kernel(const float* __restrict__ qkv,
                                                   float* __restrict__ y)
{
    extern __shared__ float sm[];
    float* qs = sm;                 // [64][65]
    float* ks = sm + 64 * 65;
    float* vs = sm + 2 * 64 * 65;
    float* ps = sm + 3 * 64 * 65;

    const int tid = threadIdx.x;
    const int blk = blockIdx.x;
    const int b = blk >> 10;          // NC_*H_ = 1024
    const int n = (blk >> 4) & 63;
    const int h = blk & 15;

    const float neg_ln_base_over_half = -9.210340371976184f / 32.0f; // -ln(10000)/32
    for (int idx = tid; idx < 64 * 32; idx += 256) {
        int r = idx >> 5;       // 0..63
        int j = idx & 31;       // 0..31
        const float* rowp = qkv + ((size_t)(b * T_ + n * 64 + r)) * 3072 + h * 64;
        float q1 = rowp[j],        q2 = rowp[j + 32];
        float k1 = rowp[1024 + j], k2 = rowp[1024 + j + 32];
        float invf = expf((float)j * neg_ln_base_over_half);   // 10000^(-j/32)
        float ang  = (float)r * invf;
        float cv, sv;
        sincosf(ang, &sv, &cv);   // sv = sin, cv = cos
        qs[r * 65 + j]      =  q1 * cv + q2 * sv;
        qs[r * 65 + j + 32] = -q1 * sv + q2 * cv;
        ks[r * 65 + j]      =  k1 * cv + k2 * sv;
        ks[r * 65 + j + 32] = -k1 * sv + k2 * cv;
    }
    for (int idx = tid; idx < 64 * 64; idx += 256) {
        int r  = idx >> 6;
        int dd = idx & 63;
        vs[r * 65 + dd] =
            qkv[((size_t)(b * T_ + n * 64 + r)) * 3072 + 2048 + h * 64 + dd];
    }
    __syncthreads();

    const int r0 = (tid >> 4) << 2;   // row block
    const int c0 = (tid & 15) << 2;   // col block (also d0 for y)

    {
        float sc[4][4];
#pragma unroll
        for (int i = 0; i < 4; i++)
#pragma unroll
            for (int j = 0; j < 4; j++) sc[i][j] = 0.0f;
#pragma unroll 8
        for (int dd = 0; dd < 64; dd++) {
            float aq[4], bk[4];
#pragma unroll
            for (int i = 0; i < 4; i++) aq[i] = qs[(r0 + i) * 65 + dd];
#pragma unroll
            for (int j = 0; j < 4; j++) bk[j] = ks[(c0 + j) * 65 + dd];
#pragma unroll
            for (int i = 0; i < 4; i++)
#pragma unroll
                for (int j = 0; j < 4; j++)
                    sc[i][j] += aq[i] * bk[j];
        }
#pragma unroll
        for (int i = 0; i < 4; i++)
#pragma unroll
            for (int j = 0; j < 4; j++)
                ps[(r0 + i) * 65 + c0 + j] = sc[i][j] * 0.125f;
    }
    __syncthreads();

    if (tid < 64) {
        float* row = ps + tid * 65;
        float mx = -1e30f;
#pragma unroll 8
        for (int c = 0; c < 64; c++) mx = fmaxf(mx, row[c]);
        float sum = 0.0f;
#pragma unroll 8
        for (int c = 0; c < 64; c++) {
            float e = expf(row[c] - mx);
            row[c] = e;
            sum += e;
        }
        float inv = 1.0f / sum;
#pragma unroll 8
        for (int c = 0; c < 64; c++) row[c] *= inv;
    }
    __syncthreads();

    {
        float acc[4][4];
#pragma unroll
        for (int i = 0; i < 4; i++)
#pragma unroll
            for (int j = 0; j < 4; j++) acc[i][j] = 0.0f;
#pragma unroll 8
        for (int c = 0; c < 64; c++) {
            float pv[4], vv[4];
#pragma unroll
            for (int i = 0; i < 4; i++) pv[i] = ps[(r0 + i) * 65 + c];
#pragma unroll
            for (int j = 0; j < 4; j++) vv[j] = vs[c * 65 + c0 + j];
#pragma unroll
            for (int i = 0; i < 4; i++)
#pragma unroll
                for (int j = 0; j < 4; j++)
                    acc[i][j] += pv[i] * vv[j];
        }
#pragma unroll
        for (int i = 0; i < 4; i++) {
            float4* yp = (float4*)(y + ((size_t)(b * T_ + n * 64 + r0 + i)) * 1024
                                     + h * 64 + c0);
            *yp = make_float4(acc[i][0], acc[i][1], acc[i][2], acc[i][3]);
        }
    }
}

// ---------------------------------------------------------------------------
extern "C" void kernel_launch(void* const* d_in, const int* in_sizes, int n_in,
                              void* d_out, int out_size)
{
    // Bind inputs BY ELEMENT COUNT (pairwise-distinct sizes):
    //   x      : 16,777,216   w_attn : 3,145,728   w_proj : 1,048,576
    const float* x      = nullptr;
    const float* w_attn = nullptr;
    const float* w_proj = nullptr;
    for (int i = 0; i < n_in; i++) {
        int sz = in_sizes[i];
        if      (sz == M_ * C_) x      = (const float*)d_in[i];
        else if (sz == F_ * C_) w_attn = (const float*)d_in[i];
        else if (sz == C_ * C_) w_proj = (const float*)d_in[i];
    }
    if (!x)      x      = (const float*)d_in[0];
    if (!w_attn) w_attn = (const float*)d_in[1];
    if (!w_proj) w_proj = (const float*)d_in[2];

    float* out = (float*)d_out;

    float *qkv_ptr, *y_ptr;
    cudaGetSymbolAddress((void**)&qkv_ptr, g_qkv);
    cudaGetSymbolAddress((void**)&y_ptr, g_y);

    const int attn_smem = 4 * 64 * 65 * sizeof(float); // 66560 bytes
    cudaFuncSetAttribute(attn_kernel, cudaFuncAttributeMaxDynamicSharedMemorySize,
                         attn_smem);

    // qkv = x @ w_attn^T   (M=16384, N=3072, K=1024)
    gemm_tn_tc<<<dim3(F_ / 128, M_ / 128), 256>>>(x, w_attn, qkv_ptr, M_, F_, C_);
    // chunked attention with RoPE
    attn_kernel<<<B_ * NC_ * H_, 256, attn_smem>>>(qkv_ptr, y_ptr);
    // out = y @ w_proj^T   (M=16384, N=1024, K=1024)
    gemm_tn_tc<<<dim3(C_ / 128, M_ / 128), 256>>>(y_ptr, w_proj, out, M_, C_, C_);
}

// round 12
// speedup vs baseline: 2.2670x; 2.2670x over previous
#include <cuda_runtime.h>
#include <cuda_bf16.h>
#include <cstdint>
#include <stdint.h>
#include <math.h>

// Problem constants
#define B_  4
#define T_  4096
#define C_  1024
#define H_  16
#define D_  64
#define CS_ 64
#define NC_ 64
#define M_  (B_ * T_)      // 16384
#define F_  (3 * C_)       // 3072

// Scratch: qkv [B,T,3C] = 192MB, y [B,T,C] = 64MB (device globals — no allocs)
__device__ float g_qkv[50331648];   // 4*4096*3072
__device__ float g_y[16777216];     // 4*4096*1024

// Split a float pair into bf16x2 hi and bf16x2 lo (lo = round(x - hi)).
__device__ __forceinline__ void split2(float x0, float x1,
                                       uint32_t& hi, uint32_t& lo) {
    __nv_bfloat162 h = __floats2bfloat162_rn(x0, x1);
    float r0 = x0 - __bfloat162float(h.x);
    float r1 = x1 - __bfloat162float(h.y);
    __nv_bfloat162 l = __floats2bfloat162_rn(r0, r1);
    hi = *(uint32_t*)&h;
    lo = *(uint32_t*)&l;
}

#define MMA_BF16(d, a, b)                                                     \
    asm volatile(                                                             \
        "mma.sync.aligned.m16n8k16.row.col.f32.bf16.bf16.f32 "                \
        "{%0,%1,%2,%3}, {%4,%5,%6,%7}, {%8,%9}, {%0,%1,%2,%3};"               \
        : "+f"(d[0]), "+f"(d[1]), "+f"(d[2]), "+f"(d[3])                      \
        : "r"(a[0]), "r"(a[1]), "r"(a[2]), "r"(a[3]), "r"(b[0]), "r"(b[1]))

// ---------------------------------------------------------------------------
// TN GEMM via tensor cores (3xBF16 split, m16n8k16): A [M,K] rm, B [N,K] rm,
// C = A @ B^T. 128x128 block tile, BK=16, 256 threads (8 warps = 4m x 2n),
// double-buffered smem, one __syncthreads per K-step.
// Smem: uint32 [buf][4 arrays][8 kpairs][136 rows]; pad 136 -> fragment
// reads conflict-free (bank = 8*tig + gid, all distinct within warp).
// ---------------------------------------------------------------------------
__global__ void __launch_bounds__(256, 1) gemm_tn_tc(const float* __restrict__ A,
                                                     const float* __restrict__ B,
                                                     float* __restrict__ C,
                                                     int M, int N, int K)
{
    // [buf][arr][kpair][row]: arr 0=A_hi, 1=A_lo, 2=B_hi, 3=B_lo
    __shared__ uint32_t sm[2][4][8][136];   // 34,816 bytes

    const int tid  = threadIdx.x;
    const int row0 = blockIdx.y * 128;
    const int col0 = blockIdx.x * 128;

    const int lane = tid & 31;
    const int warp = tid >> 5;
    const int gid  = lane >> 2;     // 0..7
    const int tig  = lane & 3;      // 0..3
    const int mb   = (warp & 3) * 32;   // warp m offset
    const int nb   = (warp >> 2) * 64;  // warp n offset

    // global-load mapping: thread handles one (row, 4k) quad, x2 row passes
    const int lr  = tid >> 2;          // 0..63 (+64 on second pass)
    const int lc4 = (tid & 3) << 2;    // 0,4,8,12
    const int kp0 = lc4 >> 1;          // 0,2,4,6

    float acc[2][8][4];
#pragma unroll
    for (int i = 0; i < 2; i++)
#pragma unroll
        for (int j = 0; j < 8; j++)
#pragma unroll
            for (int r = 0; r < 4; r++) acc[i][j][r] = 0.0f;

    const int nK = K >> 4;   // K/16 steps
    float4 pa[2], pb[2];

    // ---- prologue: load k-step 0 and stage into buffer 0 ----
#pragma unroll
    for (int it = 0; it < 2; it++) {
        int r = lr + it * 64;
        pa[it] = *(const float4*)(A + (size_t)(row0 + r) * K + lc4);
        pb[it] = *(const float4*)(B + (size_t)(col0 + r) * K + lc4);
    }
#pragma unroll
    for (int it = 0; it < 2; it++) {
        int r = lr + it * 64;
        uint32_t h0, l0, h1, l1;
        split2(pa[it].x, pa[it].y, h0, l0);
        split2(pa[it].z, pa[it].w, h1, l1);
        sm[0][0][kp0][r] = h0; sm[0][0][kp0 + 1][r] = h1;
        sm[0][1][kp0][r] = l0; sm[0][1][kp0 + 1][r] = l1;
        split2(pb[it].x, pb[it].y, h0, l0);
        split2(pb[it].z, pb[it].w, h1, l1);
        sm[0][2][kp0][r] = h0; sm[0][2][kp0 + 1][r] = h1;
        sm[0][3][kp0][r] = l0; sm[0][3][kp0 + 1][r] = l1;
    }
    __syncthreads();

    int buf = 0;
    for (int ks = 0; ks < nK; ks++) {
        const bool has_next = (ks + 1 < nK);
        // ---- prefetch next k-step into registers (latency hidden by mma) ----
        if (has_next) {
            int kg = (ks + 1) << 4;
#pragma unroll
            for (int it = 0; it < 2; it++) {
                int r = lr + it * 64;
                pa[it] = *(const float4*)(A + (size_t)(row0 + r) * K + kg + lc4);
                pb[it] = *(const float4*)(B + (size_t)(col0 + r) * K + kg + lc4);
            }
        }

        // ---- consume current buffer: 2x8 tiles x 3 mma ----
        {
            uint32_t Ah[2][4], Al[2][4];
#pragma unroll
            for (int i = 0; i < 2; i++) {
                int m0 = mb + i * 16 + gid;
                Ah[i][0] = sm[buf][0][tig][m0];
                Ah[i][1] = sm[buf][0][tig][m0 + 8];
                Ah[i][2] = sm[buf][0][tig + 4][m0];
                Ah[i][3] = sm[buf][0][tig + 4][m0 + 8];
                Al[i][0] = sm[buf][1][tig][m0];
                Al[i][1] = sm[buf][1][tig][m0 + 8];
                Al[i][2] = sm[buf][1][tig + 4][m0];
                Al[i][3] = sm[buf][1][tig + 4][m0 + 8];
            }
#pragma unroll
            for (int j = 0; j < 8; j++) {
                int n0 = nb + j * 8 + gid;
                uint32_t Bh[2], Bl[2];
                Bh[0] = sm[buf][2][tig][n0];
                Bh[1] = sm[buf][2][tig + 4][n0];
                Bl[0] = sm[buf][3][tig][n0];
                Bl[1] = sm[buf][3][tig + 4][n0];
#pragma unroll
                for (int i = 0; i < 2; i++) {
                    MMA_BF16(acc[i][j], Ah[i], Bh);   // hi*hi
                    MMA_BF16(acc[i][j], Ah[i], Bl);   // hi*lo
                    MMA_BF16(acc[i][j], Al[i], Bh);   // lo*hi
                }
            }
        }

        // ---- stage next k-step into the other buffer ----
        if (has_next) {
            int nb2 = buf ^ 1;
#pragma unroll
            for (int it = 0; it < 2; it++) {
                int r = lr + it * 64;
                uint32_t h0, l0, h1, l1;
                split2(pa[it].x, pa[it].y, h0, l0);
                split2(pa[it].z, pa[it].w, h1, l1);
                sm[nb2][0][kp0][r] = h0; sm[nb2][0][kp0 + 1][r] = h1;
                sm[nb2][1][kp0][r] = l0; sm[nb2][1][kp0 + 1][r] = l1;
                split2(pb[it].x, pb[it].y, h0, l0);
                split2(pb[it].z, pb[it].w, h1, l1);
                sm[nb2][2][kp0][r] = h0; sm[nb2][2][kp0 + 1][r] = h1;
                sm[nb2][3][kp0][r] = l0; sm[nb2][3][kp0 + 1][r] = l1;
            }
        }
        __syncthreads();
        buf ^= 1;
    }

    // epilogue: c0,c1 at (row, col..col+1); c2,c3 at (row+8, col..col+1)
#pragma unroll
    for (int i = 0; i < 2; i++) {
        int row = row0 + mb + i * 16 + gid;
#pragma unroll
        for (int j = 0; j < 8; j++) {
            int col = col0 + nb + j * 8 + tig * 2;
            *(float2*)(C + (size_t)row * N + col) =
                make_float2(acc[i][j][0], acc[i][j][1]);
            *(float2*)(C + (size_t)(row + 8) * N + col) =
                make_float2(acc[i][j][2], acc[i][j][3]);
        }
    }
}

// ---------------------------------------------------------------------------
// Fused chunked attention: one block per (b, chunk, head).
// ---------------------------------------------------------------------------
__global__ void __launch_bounds__(256) attn_kernel(const float* __restrict__ qkv,
                                                   float* __restrict__ y)
{
    extern __shared__ float smf[];
    float* qs = smf;                 // [64][65]
    float* ks = smf + 64 * 65;
    float* vs = smf + 2 * 64 * 65;
    float* ps = smf + 3 * 64 * 65;

    const int tid = threadIdx.x;
    const int blk = blockIdx.x;
    const int b = blk >> 10;          // NC_*H_ = 1024
    const int n = (blk >> 4) & 63;
    const int h = blk & 15;

    const float neg_ln_base_over_half = -9.210340371976184f / 32.0f; // -ln(10000)/32
    for (int idx = tid; idx < 64 * 32; idx += 256) {
        int r = idx >> 5;       // 0..63
        int j = idx & 31;       // 0..31
        const float* rowp = qkv + ((size_t)(b * T_ + n * 64 + r)) * 3072 + h * 64;
        float q1 = rowp[j],        q2 = rowp[j + 32];
        float k1 = rowp[1024 + j], k2 = rowp[1024 + j + 32];
        float invf = expf((float)j * neg_ln_base_over_half);   // 10000^(-j/32)
        float ang  = (float)r * invf;
        float cv, sv;
        sincosf(ang, &sv, &cv);   // sv = sin, cv = cos
        qs[r * 65 + j]      =  q1 * cv + q2 * sv;
        qs[r * 65 + j + 32] = -q1 * sv + q2 * cv;
        ks[r * 65 + j]      =  k1 * cv + k2 * sv;
        ks[r * 65 + j + 32] = -k1 * sv + k2 * cv;
    }
    for (int idx = tid; idx < 64 * 64; idx += 256) {
        int r  = idx >> 6;
        int dd = idx & 63;
        vs[r * 65 + dd] =
            qkv[((size_t)(b * T_ + n * 64 + r)) * 3072 + 2048 + h * 64 + dd];
    }
    __syncthreads();

    const int r0 = (tid >> 4) << 2;   // row block
    const int c0 = (tid & 15) << 2;   // col block (also d0 for y)

    {
        float sc[4][4];
#pragma unroll
        for (int i = 0; i < 4; i++)
#pragma unroll
            for (int j = 0; j < 4; j++) sc[i][j] = 0.0f;
#pragma unroll 8
        for (int dd = 0; dd < 64; dd++) {
            float aq[4], bk[4];
#pragma unroll
            for (int i = 0; i < 4; i++) aq[i] = qs[(r0 + i) * 65 + dd];
#pragma unroll
            for (int j = 0; j < 4; j++) bk[j] = ks[(c0 + j) * 65 + dd];
#pragma unroll
            for (int i = 0; i < 4; i++)
#pragma unroll
                for (int j = 0; j < 4; j++)
                    sc[i][j] += aq[i] * bk[j];
        }
#pragma unroll
        for (int i = 0; i < 4; i++)
#pragma unroll
            for (int j = 0; j < 4; j++)
                ps[(r0 + i) * 65 + c0 + j] = sc[i][j] * 0.125f;
    }
    __syncthreads();

    if (tid < 64) {
        float* row = ps + tid * 65;
        float mx = -1e30f;
#pragma unroll 8
        for (int c = 0; c < 64; c++) mx = fmaxf(mx, row[c]);
        float sum = 0.0f;
#pragma unroll 8
        for (int c = 0; c < 64; c++) {
            float e = expf(row[c] - mx);
            row[c] = e;
            sum += e;
        }
        float inv = 1.0f / sum;
#pragma unroll 8
        for (int c = 0; c < 64; c++) row[c] *= inv;
    }
    __syncthreads();

    {
        float acc[4][4];
#pragma unroll
        for (int i = 0; i < 4; i++)
#pragma unroll
            for (int j = 0; j < 4; j++) acc[i][j] = 0.0f;
#pragma unroll 8
        for (int c = 0; c < 64; c++) {
            float pv[4], vv[4];
#pragma unroll
            for (int i = 0; i < 4; i++) pv[i] = ps[(r0 + i) * 65 + c];
#pragma unroll
            for (int j = 0; j < 4; j++) vv[j] = vs[c * 65 + c0 + j];
#pragma unroll
            for (int i = 0; i < 4; i++)
#pragma unroll
                for (int j = 0; j < 4; j++)
                    acc[i][j] += pv[i] * vv[j];
        }
#pragma unroll
        for (int i = 0; i < 4; i++) {
            float4* yp = (float4*)(y + ((size_t)(b * T_ + n * 64 + r0 + i)) * 1024
                                     + h * 64 + c0);
            *yp = make_float4(acc[i][0], acc[i][1], acc[i][2], acc[i][3]);
        }
    }
}

// ---------------------------------------------------------------------------
extern "C" void kernel_launch(void* const* d_in, const int* in_sizes, int n_in,
                              void* d_out, int out_size)
{
    // Bind inputs BY ELEMENT COUNT (pairwise-distinct sizes):
    //   x      : 16,777,216   w_attn : 3,145,728   w_proj : 1,048,576
    const float* x      = nullptr;
    const float* w_attn = nullptr;
    const float* w_proj = nullptr;
    for (int i = 0; i < n_in; i++) {
        int sz = in_sizes[i];
        if      (sz == M_ * C_) x      = (const float*)d_in[i];
        else if (sz == F_ * C_) w_attn = (const float*)d_in[i];
        else if (sz == C_ * C_) w_proj = (const float*)d_in[i];
    }
    if (!x)      x      = (const float*)d_in[0];
    if (!w_attn) w_attn = (const float*)d_in[1];
    if (!w_proj) w_proj = (const float*)d_in[2];

    float* out = (float*)d_out;

    float *qkv_ptr, *y_ptr;
    cudaGetSymbolAddress((void**)&qkv_ptr, g_qkv);
    cudaGetSymbolAddress((void**)&y_ptr, g_y);

    const int attn_smem = 4 * 64 * 65 * sizeof(float); // 66560 bytes
    cudaFuncSetAttribute(attn_kernel, cudaFuncAttributeMaxDynamicSharedMemorySize,
                         attn_smem);

    // qkv = x @ w_attn^T   (M=16384, N=3072, K=1024)
    gemm_tn_tc<<<dim3(F_ / 128, M_ / 128), 256>>>(x, w_attn, qkv_ptr, M_, F_, C_);
    // chunked attention with RoPE
    attn_kernel<<<B_ * NC_ * H_, 256, attn_smem>>>(qkv_ptr, y_ptr);
    // out = y @ w_proj^T   (M=16384, N=1024, K=1024)
    gemm_tn_tc<<<dim3(C_ / 128, M_ / 128), 256>>>(y_ptr, w_proj, out, M_, C_, C_);
}